// round 13
// baseline (speedup 1.0000x reference)
#include <cuda_runtime.h>
#include <cuda_bf16.h>
#include <math.h>

typedef unsigned int u32;

#define RADIUS_F 1.3f
#define STEPSZ   0.02f

// ---------------- global scratch (no allocs allowed) ----------------
__device__ float g_Ft[131072];      // F transposed (idx, 32ch)
__device__ u32   g_pack[14592];     // all weights in bf16 B-fragment order

// pack-buffer bases (u32 units)
#define PB_L0 0        // W0  K=32  N=128  KT=2 NT=16 -> 2048
#define PB_L1 2048     // W1  K=128 N=128  KT=8 NT=16 -> 8192
#define PB_L2 10240    // W2  K=128 N=16   KT=8 NT=2  -> 1024 (cols rotated; col15 = sigma)
#define PB_C0 11264    // Wc0 K=32(31+pad) N=64 KT=2 NT=8 -> 1024
#define PB_C1 12288    // Wc1 K=64  N=64   KT=4 NT=8 -> 2048
#define PB_C2 14336    // Wc2 K=64  N=8(3+pad) KT=4 NT=1 -> 256

// ---------------- single merged prep kernel ----------------
__device__ __forceinline__ void pack_one(const float* __restrict__ W, int base, int j,
                                         int KT, int Korig, int Norig, int rowstride,
                                         int sig_reorder)
{
    int r    = j & 1;
    int lane = (j >> 1) & 31;
    int t    = j >> 6;           // = nt*KT + kt
    int kt   = t % KT;
    int nt   = t / KT;
    int k = kt*16 + (lane & 3)*2 + r*8;
    int n = nt*8 + (lane >> 2);
    int nc = sig_reorder ? ((n == 15) ? 0 : n + 1) : n;
    float w0 = (k     < Korig && nc < Norig) ? W[k*rowstride + nc]     : 0.0f;
    float w1 = (k + 1 < Korig && nc < Norig) ? W[(k+1)*rowstride + nc] : 0.0f;
    __nv_bfloat162 p = __floats2bfloat162_rn(w0, w1);
    g_pack[base + j] = *(u32*)&p;
}

__global__ void prep_kernel(const float* __restrict__ F,
                            const float* __restrict__ W0,
                            const float* __restrict__ W1,
                            const float* __restrict__ W2,
                            const float* __restrict__ Wc0,
                            const float* __restrict__ Wc1,
                            const float* __restrict__ Wc2)
{
    int idx = blockIdx.x * blockDim.x + threadIdx.x;
    if (idx < 131072) {
        int ch  = idx >> 12;
        int e   = idx & 4095;
        g_Ft[e * 32 + ch] = F[idx];
        return;
    }
    int j = idx - 131072;
    if (j < 2048)       pack_one(W0,  PB_L0, j,         2, 32,  128, 128, 0);
    else if (j < 10240) pack_one(W1,  PB_L1, j - 2048,  8, 128, 128, 128, 0);
    else if (j < 11264) pack_one(W2,  PB_L2, j - 10240, 8, 128, 16,  16,  1);
    else if (j < 12288) pack_one(Wc0, PB_C0, j - 11264, 2, 31,  64,  64,  0);
    else if (j < 14336) pack_one(Wc1, PB_C1, j - 12288, 4, 64,  64,  64,  0);
    else if (j < 14592) pack_one(Wc2, PB_C2, j - 14336, 4, 64,  3,   3,   0);
}

// ---------------- device helpers ----------------
__device__ __forceinline__ u32 packbf(float lo, float hi) {
    __nv_bfloat162 p = __floats2bfloat162_rn(lo, hi);
    return *(u32*)&p;
}
__device__ __forceinline__ u32 packbf_relu(float lo, float hi) {
    return packbf(fmaxf(lo, 0.0f), fmaxf(hi, 0.0f));
}
__device__ __forceinline__ void mma_bf16(float* d, const u32* a, const u32* b) {
    asm volatile(
        "mma.sync.aligned.m16n8k16.row.col.f32.bf16.bf16.f32 "
        "{%0,%1,%2,%3},{%4,%5,%6,%7},{%8,%9},{%0,%1,%2,%3};"
        : "+f"(d[0]), "+f"(d[1]), "+f"(d[2]), "+f"(d[3])
        : "r"(a[0]), "r"(a[1]), "r"(a[2]), "r"(a[3]), "r"(b[0]), "r"(b[1]));
}
__device__ __forceinline__ void ldb(u32* b, int base, int nt, int kt, int KT, int lane) {
    const uint2* p = (const uint2*)(g_pack + base + (((nt*KT + kt) << 5) + lane)*2);
    uint2 v = __ldg(p);
    b[0] = v.x; b[1] = v.y;
}
__device__ __forceinline__ float sigm(float v) {
    return __fdividef(1.0f, 1.0f + __expf(-v));
}

// G1 trilinear (3ch, 256^3) then F trilinear (32ch via g_Ft) -> x[32]
__device__ __forceinline__ void sample_feats(const float* __restrict__ G1,
                                             float px, float py, float pz,
                                             float* __restrict__ x)
{
    float gi[3];
    {
        float fx = fminf(fmaxf((px + 1.0f)*0.5f*255.0f, 0.0f), 255.0f);
        float fy = fminf(fmaxf((py + 1.0f)*0.5f*255.0f, 0.0f), 255.0f);
        float fz = fminf(fmaxf((pz + 1.0f)*0.5f*255.0f, 0.0f), 255.0f);
        int x0 = (int)floorf(fx), y0 = (int)floorf(fy), z0 = (int)floorf(fz);
        int x1 = min(x0+1, 255), y1 = min(y0+1, 255), z1 = min(z0+1, 255);
        float wx = fx - (float)x0, wy = fy - (float)y0, wz = fz - (float)z0;
        int o00 = z0*65536 + y0*256;
        int o01 = z0*65536 + y1*256;
        int o10 = z1*65536 + y0*256;
        int o11 = z1*65536 + y1*256;
        #pragma unroll
        for (int ch = 0; ch < 3; ch++) {
            const float* g = G1 + ch*16777216;
            float v000 = __ldg(g + o00 + x0), v001 = __ldg(g + o00 + x1);
            float v010 = __ldg(g + o01 + x0), v011 = __ldg(g + o01 + x1);
            float v100 = __ldg(g + o10 + x0), v101 = __ldg(g + o10 + x1);
            float v110 = __ldg(g + o11 + x0), v111 = __ldg(g + o11 + x1);
            float c00 = v000*(1.0f-wx) + v001*wx;
            float c01 = v010*(1.0f-wx) + v011*wx;
            float c10 = v100*(1.0f-wx) + v101*wx;
            float c11 = v110*(1.0f-wx) + v111*wx;
            float c0  = c00*(1.0f-wy) + c01*wy;
            float c1  = c10*(1.0f-wy) + c11*wy;
            gi[ch] = c0*(1.0f-wz) + c1*wz;
        }
    }
    {
        float fx = fminf(fmaxf((gi[0] + 1.0f)*7.5f, 0.0f), 15.0f);
        float fy = fminf(fmaxf((gi[1] + 1.0f)*7.5f, 0.0f), 15.0f);
        float fz = fminf(fmaxf((gi[2] + 1.0f)*7.5f, 0.0f), 15.0f);
        int x0 = (int)floorf(fx), y0 = (int)floorf(fy), z0 = (int)floorf(fz);
        int x1 = min(x0+1, 15), y1 = min(y0+1, 15), z1 = min(z0+1, 15);
        float wx = fx - (float)x0, wy = fy - (float)y0, wz = fz - (float)z0;
        float mx = 1.0f - wx, my = 1.0f - wy, mz = 1.0f - wz;
        float w000 = mx*my*mz, w001 = wx*my*mz;
        float w010 = mx*wy*mz, w011 = wx*wy*mz;
        float w100 = mx*my*wz, w101 = wx*my*wz;
        float w110 = mx*wy*wz, w111 = wx*wy*wz;
        const float4* fb = (const float4*)g_Ft;
        int b000 = (z0*256 + y0*16 + x0)*8;
        int b001 = (z0*256 + y0*16 + x1)*8;
        int b010 = (z0*256 + y1*16 + x0)*8;
        int b011 = (z0*256 + y1*16 + x1)*8;
        int b100 = (z1*256 + y0*16 + x0)*8;
        int b101 = (z1*256 + y0*16 + x1)*8;
        int b110 = (z1*256 + y1*16 + x0)*8;
        int b111 = (z1*256 + y1*16 + x1)*8;
        #pragma unroll
        for (int q = 0; q < 8; q++) {
            float4 v = __ldg(fb + b000 + q);
            float ax = v.x*w000, ay = v.y*w000, az = v.z*w000, aw = v.w*w000;
            v = __ldg(fb + b001 + q);
            ax = fmaf(v.x, w001, ax); ay = fmaf(v.y, w001, ay);
            az = fmaf(v.z, w001, az); aw = fmaf(v.w, w001, aw);
            v = __ldg(fb + b010 + q);
            ax = fmaf(v.x, w010, ax); ay = fmaf(v.y, w010, ay);
            az = fmaf(v.z, w010, az); aw = fmaf(v.w, w010, aw);
            v = __ldg(fb + b011 + q);
            ax = fmaf(v.x, w011, ax); ay = fmaf(v.y, w011, ay);
            az = fmaf(v.z, w011, az); aw = fmaf(v.w, w011, aw);
            v = __ldg(fb + b100 + q);
            ax = fmaf(v.x, w100, ax); ay = fmaf(v.y, w100, ay);
            az = fmaf(v.z, w100, az); aw = fmaf(v.w, w100, aw);
            v = __ldg(fb + b101 + q);
            ax = fmaf(v.x, w101, ax); ay = fmaf(v.y, w101, ay);
            az = fmaf(v.z, w101, az); aw = fmaf(v.w, w101, aw);
            v = __ldg(fb + b110 + q);
            ax = fmaf(v.x, w110, ax); ay = fmaf(v.y, w110, ay);
            az = fmaf(v.z, w110, az); aw = fmaf(v.w, w110, aw);
            v = __ldg(fb + b111 + q);
            ax = fmaf(v.x, w111, ax); ay = fmaf(v.y, w111, ay);
            az = fmaf(v.z, w111, az); aw = fmaf(v.w, w111, aw);
            x[4*q+0] = ax; x[4*q+1] = ay; x[4*q+2] = az; x[4*q+3] = aw;
        }
    }
}

// ---------------- main fused kernel: 1 block = 2 rays, 256 threads ----------------
#define XP 20   // u32 pitch of X rows (conflict-free fragment loads)

__global__ __launch_bounds__(256, 2)
void nerf_mma3(const float* __restrict__ rays_o,
               const float* __restrict__ rays_d,
               const float* __restrict__ G1,
               float* __restrict__ outp)
{
    __shared__ u32   Xs[256*XP];     // X features (2 rays x 128 samples), row = tid
    __shared__ float shE[2][16];     // SH encoding per ray
    __shared__ u32   shAmask;        // bit t = tile t active (16 tiles)
    __shared__ float sigs[256];      // raw sigma per combined sample
    __shared__ float rgbs[256][4];   // sigmoid(col) per combined sample

    const int tid  = threadIdx.x;
    const int half = tid >> 7;                 // which ray of the pair
    const int ray  = blockIdx.x*2 + half;

    const float ox = rays_o[ray*3+0], oy = rays_o[ray*3+1], oz = rays_o[ray*3+2];
    float dx = rays_d[ray*3+0], dy = rays_d[ray*3+1], dz = rays_d[ray*3+2];
    const float dn = sqrtf(dx*dx + dy*dy + dz*dz);
    dx /= dn; dy /= dn; dz /= dn;

    const float b  = ox*dx + oy*dy + oz*dz;
    const float cc = ox*ox + oy*oy + oz*oz - RADIUS_F*RADIUS_F;
    const float disc = b*b - cc;
    const bool hit = disc > 0.0f;
    const float sq = sqrtf(hit ? disc : 1.0f);
    const float tmin = hit ? fmaxf(-b - sq, 0.0f) : 0.0f;
    const float tmax = hit ? (-b + sq) : 0.0f;

    const int s = tid & 127;   // sample index within this ray

    // ---- per-ray uniforms to shared (one thread per ray)
    if (s == 0) {
        const float x = dx, y = dy, z = dz;
        const float xx = x*x, yy = y*y, zz = z*z;
        const float xy = x*y, yz = y*z, xz = x*z;
        float* E = shE[half];
        E[0]  = 0.28209479177387814f;
        E[1]  = -0.48860251190291987f*y;
        E[2]  =  0.48860251190291987f*z;
        E[3]  = -0.48860251190291987f*x;
        E[4]  =  1.0925484305920792f*xy;
        E[5]  = -1.0925484305920792f*yz;
        E[6]  =  0.94617469575756f*zz - 0.31539156525252f;
        E[7]  = -1.0925484305920792f*xz;
        E[8]  =  0.5462742152960396f*(xx - yy);
        E[9]  =  0.5900435899266435f*y*(-3.0f*xx + yy);
        E[10] =  2.890611442640554f*xy*z;
        E[11] =  0.4570457994644657f*y*(1.0f - 5.0f*zz);
        E[12] =  0.3731763325901154f*z*(5.0f*zz - 3.0f);
        E[13] =  0.4570457994644657f*x*(1.0f - 5.0f*zz);
        E[14] =  1.445305721320277f*z*(xx - yy);
        E[15] =  0.5900435899266435f*x*(-xx + 3.0f*yy);
    }

    // ---- tile-active bitmask: sample s is active iff tmid(s) <= tmax;
    // tile t (16 samples) active iff its first sample is active (prefix property).
    // Threads 0 and 128 see their own ray's tmin/tmax; use lanes of warp 0 via shuffle?
    // Simpler: every thread evaluates activity of its own sample; tile flag taken
    // from the sample at the tile start (s % 16 == 0) -> ballot in each warp of the
    // first 4 warps won't span both rays. Use: thread tid = t*16 evaluates tile t.
    {
        const bool tile_lead = ((tid & 15) == 0);            // tids 0,16,...,240
        const bool act = hit && (tmin + ((float)s + 0.5f)*STEPSZ <= tmax);
        // warp 0 gathers: tile t lead is tid t*16, in warp t/2. Too scattered for
        // one ballot -> write flags to shared via atomic-free OR built by warp 0.
        __shared__ u32 leadFlags[16];
        if (tile_lead) leadFlags[tid >> 4] = act ? 1u : 0u;
        __syncthreads();
        if (tid == 0) {
            u32 m = 0;
            #pragma unroll
            for (int t = 0; t < 16; t++) m |= leadFlags[t] << t;
            shAmask = m;
        }
    }

    // ---- sampling phase: ALL 256 threads, one sample each (combined row = tid)
    {
        const float tmid = tmin + ((float)s + 0.5f) * STEPSZ;
        const bool m = hit && (tmid <= tmax);
        u32* xrow = Xs + tid*XP;
        if (m) {
            float xf[32];
            sample_feats(G1, (ox + dx*tmid)/RADIUS_F, (oy + dy*tmid)/RADIUS_F,
                         (oz + dz*tmid)/RADIUS_F, xf);
            #pragma unroll
            for (int i = 0; i < 16; i++) xrow[i] = packbf(xf[2*i], xf[2*i+1]);
        } else {
            // clean state for (possibly skipped) masked samples
            #pragma unroll
            for (int i = 0; i < 16; i++) xrow[i] = 0u;
            sigs[tid] = 0.0f;
            rgbs[tid][0] = 0.0f; rgbs[tid][1] = 0.0f; rgbs[tid][2] = 0.0f;
        }
    }
    __syncthreads();

    // ---- MLP phase with tile compaction: warp w takes the (w)-th and (w+8)-th
    // ACTIVE tiles (set bits of shAmask). Balanced: block critical path =
    // ceil(popc(amask)/8) tile passes instead of 2.
    {
        const int wid = tid >> 5, lane = tid & 31;
        const int r = lane >> 2, c = lane & 3;
        const u32 amask = shAmask;

        #pragma unroll
        for (int ti = 0; ti < 2; ti++) {
            const int j = wid + ti*8;                 // j-th active tile wanted
            const int t = (int)__fns(amask, 0, j+1);  // position of (j+1)-th set bit
            if (t < 0 || t > 15) continue;
            const int rIdx = t >> 3;

            const int s0 = t*16 + r, s1 = s0 + 8;
            u32 bfr[2];

            // A fragments of X (K=32 -> 2 k-tiles)
            u32 aX[2][4];
            #pragma unroll
            for (int kt = 0; kt < 2; kt++) {
                aX[kt][0] = Xs[s0*XP + kt*8 + c];
                aX[kt][1] = Xs[s1*XP + kt*8 + c];
                aX[kt][2] = Xs[s0*XP + kt*8 + c + 4];
                aX[kt][3] = Xs[s1*XP + kt*8 + c + 4];
            }

            // ---- L0: X(16x32) @ W0 -> 16x128
            float acc[16][4];
            #pragma unroll
            for (int nt = 0; nt < 16; nt++) {
                acc[nt][0] = acc[nt][1] = acc[nt][2] = acc[nt][3] = 0.0f;
                #pragma unroll
                for (int kt = 0; kt < 2; kt++) {
                    ldb(bfr, PB_L0, nt, kt, 2, lane);
                    mma_bf16(acc[nt], aX[kt], bfr);
                }
            }
            u32 ah[8][4];
            #pragma unroll
            for (int kt = 0; kt < 8; kt++) {
                ah[kt][0] = packbf_relu(acc[2*kt][0],   acc[2*kt][1]);
                ah[kt][1] = packbf_relu(acc[2*kt][2],   acc[2*kt][3]);
                ah[kt][2] = packbf_relu(acc[2*kt+1][0], acc[2*kt+1][1]);
                ah[kt][3] = packbf_relu(acc[2*kt+1][2], acc[2*kt+1][3]);
            }

            // ---- L1: H1 @ W1 -> 16x128
            #pragma unroll
            for (int nt = 0; nt < 16; nt++) {
                acc[nt][0] = acc[nt][1] = acc[nt][2] = acc[nt][3] = 0.0f;
                #pragma unroll
                for (int kt = 0; kt < 8; kt++) {
                    ldb(bfr, PB_L1, nt, kt, 8, lane);
                    mma_bf16(acc[nt], ah[kt], bfr);
                }
            }
            #pragma unroll
            for (int kt = 0; kt < 8; kt++) {
                ah[kt][0] = packbf_relu(acc[2*kt][0],   acc[2*kt][1]);
                ah[kt][1] = packbf_relu(acc[2*kt][2],   acc[2*kt][3]);
                ah[kt][2] = packbf_relu(acc[2*kt+1][0], acc[2*kt+1][1]);
                ah[kt][3] = packbf_relu(acc[2*kt+1][2], acc[2*kt+1][3]);
            }

            // ---- L2: H2 @ W2' -> 16x16  (cols rotated; col15 = sigma)
            float dsig[2][4];
            #pragma unroll
            for (int nt = 0; nt < 2; nt++) {
                dsig[nt][0] = dsig[nt][1] = dsig[nt][2] = dsig[nt][3] = 0.0f;
                #pragma unroll
                for (int kt = 0; kt < 8; kt++) {
                    ldb(bfr, PB_L2, nt, kt, 8, lane);
                    mma_bf16(dsig[nt], ah[kt], bfr);
                }
            }
            if (c == 3) {
                sigs[s0] = dsig[1][1];
                sigs[s1] = dsig[1][3];
            }

            // ---- color input fragments: k-tile0 = enc (uniform rows), k-tile1 = dsig raw
            u32 ae0[4], ae1[4];
            {
                const float* E = shE[rIdx];
                u32 lo = packbf(E[2*c],     E[2*c+1]);
                u32 hi = packbf(E[8 + 2*c], E[9 + 2*c]);
                ae0[0] = lo; ae0[1] = lo; ae0[2] = hi; ae0[3] = hi;
            }
            ae1[0] = packbf(dsig[0][0], dsig[0][1]);
            ae1[1] = packbf(dsig[0][2], dsig[0][3]);
            ae1[2] = packbf(dsig[1][0], dsig[1][1]);
            ae1[3] = packbf(dsig[1][2], dsig[1][3]);

            // ---- C0: Cin(16x32) @ Wc0 -> 16x64
            float dc[8][4];
            #pragma unroll
            for (int nt = 0; nt < 8; nt++) {
                dc[nt][0] = dc[nt][1] = dc[nt][2] = dc[nt][3] = 0.0f;
                ldb(bfr, PB_C0, nt, 0, 2, lane); mma_bf16(dc[nt], ae0, bfr);
                ldb(bfr, PB_C0, nt, 1, 2, lane); mma_bf16(dc[nt], ae1, bfr);
            }
            u32 ag[4][4];
            #pragma unroll
            for (int kt = 0; kt < 4; kt++) {
                ag[kt][0] = packbf_relu(dc[2*kt][0],   dc[2*kt][1]);
                ag[kt][1] = packbf_relu(dc[2*kt][2],   dc[2*kt][3]);
                ag[kt][2] = packbf_relu(dc[2*kt+1][0], dc[2*kt+1][1]);
                ag[kt][3] = packbf_relu(dc[2*kt+1][2], dc[2*kt+1][3]);
            }

            // ---- C1: G1h @ Wc1 -> 16x64
            #pragma unroll
            for (int nt = 0; nt < 8; nt++) {
                dc[nt][0] = dc[nt][1] = dc[nt][2] = dc[nt][3] = 0.0f;
                #pragma unroll
                for (int kt = 0; kt < 4; kt++) {
                    ldb(bfr, PB_C1, nt, kt, 4, lane);
                    mma_bf16(dc[nt], ag[kt], bfr);
                }
            }
            #pragma unroll
            for (int kt = 0; kt < 4; kt++) {
                ag[kt][0] = packbf_relu(dc[2*kt][0],   dc[2*kt][1]);
                ag[kt][1] = packbf_relu(dc[2*kt][2],   dc[2*kt][3]);
                ag[kt][2] = packbf_relu(dc[2*kt+1][0], dc[2*kt+1][1]);
                ag[kt][3] = packbf_relu(dc[2*kt+1][2], dc[2*kt+1][3]);
            }

            // ---- C2: G2h @ Wc2 -> 16x8 (cols 0,1,2 = r,g,b)
            float drgb[4] = {0.0f, 0.0f, 0.0f, 0.0f};
            #pragma unroll
            for (int kt = 0; kt < 4; kt++) {
                ldb(bfr, PB_C2, 0, kt, 4, lane);
                mma_bf16(drgb, ag[kt], bfr);
            }
            if (c == 0) {   // cols 0,1 -> R,G
                rgbs[s0][0] = sigm(drgb[0]); rgbs[s0][1] = sigm(drgb[1]);
                rgbs[s1][0] = sigm(drgb[2]); rgbs[s1][1] = sigm(drgb[3]);
            }
            if (c == 1) {   // col 2 -> B
                rgbs[s0][2] = sigm(drgb[0]);
                rgbs[s1][2] = sigm(drgb[2]);
            }
        }
    }
    __syncthreads();

    // ---- compositing: warp 0 -> ray0, warp 1 -> ray1 (parallel scan)
    if (tid < 64) {
        const int rIdx = tid >> 5;
        const int lane = tid & 31;
        const int base = rIdx * 128;
        float Tl = 1.0f;
        float rr = 0.0f, gg = 0.0f, bb = 0.0f, ws = 0.0f;
        #pragma unroll
        for (int j = 0; j < 4; j++) {
            const int i = base + lane*4 + j;
            const float sg = fmaxf(sigs[i], 0.0f);
            const float a  = 1.0f - __expf(-sg * STEPSZ);
            const float w  = a * Tl;
            rr += w * rgbs[i][0];
            gg += w * rgbs[i][1];
            bb += w * rgbs[i][2];
            ws += w;
            Tl *= (1.0f - a + 1e-10f);
        }
        float inc = Tl;
        #pragma unroll
        for (int off = 1; off < 32; off <<= 1) {
            float v = __shfl_up_sync(0xFFFFFFFFu, inc, off);
            if (lane >= off) inc *= v;
        }
        float exc = __shfl_up_sync(0xFFFFFFFFu, inc, 1);
        if (lane == 0) exc = 1.0f;
        rr *= exc; gg *= exc; bb *= exc; ws *= exc;
        #pragma unroll
        for (int off = 16; off > 0; off >>= 1) {
            rr += __shfl_down_sync(0xFFFFFFFFu, rr, off);
            gg += __shfl_down_sync(0xFFFFFFFFu, gg, off);
            bb += __shfl_down_sync(0xFFFFFFFFu, bb, off);
            ws += __shfl_down_sync(0xFFFFFFFFu, ws, off);
        }
        if (lane == 0) {
            const int oray = blockIdx.x*2 + rIdx;
            const float bg = 1.0f - ws;
            outp[oray*3+0] = rr + bg;
            outp[oray*3+1] = gg + bg;
            outp[oray*3+2] = bb + bg;
        }
    }
}

// ---------------- launch ----------------
extern "C" void kernel_launch(void* const* d_in, const int* in_sizes, int n_in,
                              void* d_out, int out_size)
{
    const float* rays_o = (const float*)d_in[0];
    const float* rays_d = (const float*)d_in[1];
    const float* G1     = (const float*)d_in[2];
    const float* F      = (const float*)d_in[3];
    const float* W0     = (const float*)d_in[4];
    const float* W1     = (const float*)d_in[5];
    const float* W2     = (const float*)d_in[6];
    const float* Wc0    = (const float*)d_in[7];
    const float* Wc1    = (const float*)d_in[8];
    const float* Wc2    = (const float*)d_in[9];
    float* outp = (float*)d_out;

    const int B = in_sizes[0] / 3;

    prep_kernel<<<(131072 + 14592 + 255)/256, 256>>>(F, W0, W1, W2, Wc0, Wc1, Wc2);

    nerf_mma3<<<B/2, 256>>>(rays_o, rays_d, G1, outp);
}

// round 14
// speedup vs baseline: 1.0997x; 1.0997x over previous
#include <cuda_runtime.h>
#include <cuda_bf16.h>
#include <math.h>

typedef unsigned int u32;

#define RADIUS_F 1.3f
#define STEPSZ   0.02f

// ---------------- global scratch (no allocs allowed) ----------------
__device__ float g_Ft[131072];      // F transposed (idx, 32ch)
__device__ u32   g_pack[14592];     // all weights in bf16 B-fragment order

// pack-buffer bases (u32 units)
#define PB_L0 0        // W0  K=32  N=128  KT=2 NT=16 -> 2048
#define PB_L1 2048     // W1  K=128 N=128  KT=8 NT=16 -> 8192
#define PB_L2 10240    // W2  K=128 N=16   KT=8 NT=2  -> 1024 (cols rotated; col15 = sigma)
#define PB_C0 11264    // Wc0 K=32(31+pad) N=64 KT=2 NT=8 -> 1024
#define PB_C1 12288    // Wc1 K=64  N=64   KT=4 NT=8 -> 2048
#define PB_C2 14336    // Wc2 K=64  N=8(3+pad) KT=4 NT=1 -> 256

// ---------------- single merged prep kernel ----------------
__device__ __forceinline__ void pack_one(const float* __restrict__ W, int base, int j,
                                         int KT, int Korig, int Norig, int rowstride,
                                         int sig_reorder)
{
    int r    = j & 1;
    int lane = (j >> 1) & 31;
    int t    = j >> 6;           // = nt*KT + kt
    int kt   = t % KT;
    int nt   = t / KT;
    int k = kt*16 + (lane & 3)*2 + r*8;
    int n = nt*8 + (lane >> 2);
    int nc = sig_reorder ? ((n == 15) ? 0 : n + 1) : n;
    float w0 = (k     < Korig && nc < Norig) ? W[k*rowstride + nc]     : 0.0f;
    float w1 = (k + 1 < Korig && nc < Norig) ? W[(k+1)*rowstride + nc] : 0.0f;
    __nv_bfloat162 p = __floats2bfloat162_rn(w0, w1);
    g_pack[base + j] = *(u32*)&p;
}

__global__ void prep_kernel(const float* __restrict__ F,
                            const float* __restrict__ W0,
                            const float* __restrict__ W1,
                            const float* __restrict__ W2,
                            const float* __restrict__ Wc0,
                            const float* __restrict__ Wc1,
                            const float* __restrict__ Wc2)
{
    int idx = blockIdx.x * blockDim.x + threadIdx.x;
    if (idx < 131072) {
        int ch  = idx >> 12;
        int e   = idx & 4095;
        g_Ft[e * 32 + ch] = F[idx];
        return;
    }
    int j = idx - 131072;
    if (j < 2048)       pack_one(W0,  PB_L0, j,         2, 32,  128, 128, 0);
    else if (j < 10240) pack_one(W1,  PB_L1, j - 2048,  8, 128, 128, 128, 0);
    else if (j < 11264) pack_one(W2,  PB_L2, j - 10240, 8, 128, 16,  16,  1);
    else if (j < 12288) pack_one(Wc0, PB_C0, j - 11264, 2, 31,  64,  64,  0);
    else if (j < 14336) pack_one(Wc1, PB_C1, j - 12288, 4, 64,  64,  64,  0);
    else if (j < 14592) pack_one(Wc2, PB_C2, j - 14336, 4, 64,  3,   3,   0);
}

// ---------------- device helpers ----------------
__device__ __forceinline__ u32 packbf(float lo, float hi) {
    __nv_bfloat162 p = __floats2bfloat162_rn(lo, hi);
    return *(u32*)&p;
}
__device__ __forceinline__ u32 packbf_relu(float lo, float hi) {
    return packbf(fmaxf(lo, 0.0f), fmaxf(hi, 0.0f));
}
__device__ __forceinline__ void mma_bf16(float* d, const u32* a, const u32* b) {
    asm volatile(
        "mma.sync.aligned.m16n8k16.row.col.f32.bf16.bf16.f32 "
        "{%0,%1,%2,%3},{%4,%5,%6,%7},{%8,%9},{%0,%1,%2,%3};"
        : "+f"(d[0]), "+f"(d[1]), "+f"(d[2]), "+f"(d[3])
        : "r"(a[0]), "r"(a[1]), "r"(a[2]), "r"(a[3]), "r"(b[0]), "r"(b[1]));
}
__device__ __forceinline__ void ldb(u32* b, int base, int nt, int kt, int KT, int lane) {
    const uint2* p = (const uint2*)(g_pack + base + (((nt*KT + kt) << 5) + lane)*2);
    uint2 v = __ldg(p);
    b[0] = v.x; b[1] = v.y;
}
__device__ __forceinline__ float sigm(float v) {
    return __fdividef(1.0f, 1.0f + __expf(-v));
}

// G1 trilinear (3ch, 256^3) then F trilinear (32ch via g_Ft) -> x[32]
__device__ __forceinline__ void sample_feats(const float* __restrict__ G1,
                                             float px, float py, float pz,
                                             float* __restrict__ x)
{
    float gi[3];
    {
        float fx = fminf(fmaxf((px + 1.0f)*0.5f*255.0f, 0.0f), 255.0f);
        float fy = fminf(fmaxf((py + 1.0f)*0.5f*255.0f, 0.0f), 255.0f);
        float fz = fminf(fmaxf((pz + 1.0f)*0.5f*255.0f, 0.0f), 255.0f);
        int x0 = (int)floorf(fx), y0 = (int)floorf(fy), z0 = (int)floorf(fz);
        int x1 = min(x0+1, 255), y1 = min(y0+1, 255), z1 = min(z0+1, 255);
        float wx = fx - (float)x0, wy = fy - (float)y0, wz = fz - (float)z0;
        int o00 = z0*65536 + y0*256;
        int o01 = z0*65536 + y1*256;
        int o10 = z1*65536 + y0*256;
        int o11 = z1*65536 + y1*256;
        #pragma unroll
        for (int ch = 0; ch < 3; ch++) {
            const float* g = G1 + ch*16777216;
            float v000 = __ldg(g + o00 + x0), v001 = __ldg(g + o00 + x1);
            float v010 = __ldg(g + o01 + x0), v011 = __ldg(g + o01 + x1);
            float v100 = __ldg(g + o10 + x0), v101 = __ldg(g + o10 + x1);
            float v110 = __ldg(g + o11 + x0), v111 = __ldg(g + o11 + x1);
            float c00 = v000*(1.0f-wx) + v001*wx;
            float c01 = v010*(1.0f-wx) + v011*wx;
            float c10 = v100*(1.0f-wx) + v101*wx;
            float c11 = v110*(1.0f-wx) + v111*wx;
            float c0  = c00*(1.0f-wy) + c01*wy;
            float c1  = c10*(1.0f-wy) + c11*wy;
            gi[ch] = c0*(1.0f-wz) + c1*wz;
        }
    }
    {
        float fx = fminf(fmaxf((gi[0] + 1.0f)*7.5f, 0.0f), 15.0f);
        float fy = fminf(fmaxf((gi[1] + 1.0f)*7.5f, 0.0f), 15.0f);
        float fz = fminf(fmaxf((gi[2] + 1.0f)*7.5f, 0.0f), 15.0f);
        int x0 = (int)floorf(fx), y0 = (int)floorf(fy), z0 = (int)floorf(fz);
        int x1 = min(x0+1, 15), y1 = min(y0+1, 15), z1 = min(z0+1, 15);
        float wx = fx - (float)x0, wy = fy - (float)y0, wz = fz - (float)z0;
        float mx = 1.0f - wx, my = 1.0f - wy, mz = 1.0f - wz;
        float w000 = mx*my*mz, w001 = wx*my*mz;
        float w010 = mx*wy*mz, w011 = wx*wy*mz;
        float w100 = mx*my*wz, w101 = wx*my*wz;
        float w110 = mx*wy*wz, w111 = wx*wy*wz;
        const float4* fb = (const float4*)g_Ft;
        int b000 = (z0*256 + y0*16 + x0)*8;
        int b001 = (z0*256 + y0*16 + x1)*8;
        int b010 = (z0*256 + y1*16 + x0)*8;
        int b011 = (z0*256 + y1*16 + x1)*8;
        int b100 = (z1*256 + y0*16 + x0)*8;
        int b101 = (z1*256 + y0*16 + x1)*8;
        int b110 = (z1*256 + y1*16 + x0)*8;
        int b111 = (z1*256 + y1*16 + x1)*8;
        #pragma unroll
        for (int q = 0; q < 8; q++) {
            float4 v = __ldg(fb + b000 + q);
            float ax = v.x*w000, ay = v.y*w000, az = v.z*w000, aw = v.w*w000;
            v = __ldg(fb + b001 + q);
            ax = fmaf(v.x, w001, ax); ay = fmaf(v.y, w001, ay);
            az = fmaf(v.z, w001, az); aw = fmaf(v.w, w001, aw);
            v = __ldg(fb + b010 + q);
            ax = fmaf(v.x, w010, ax); ay = fmaf(v.y, w010, ay);
            az = fmaf(v.z, w010, az); aw = fmaf(v.w, w010, aw);
            v = __ldg(fb + b011 + q);
            ax = fmaf(v.x, w011, ax); ay = fmaf(v.y, w011, ay);
            az = fmaf(v.z, w011, az); aw = fmaf(v.w, w011, aw);
            v = __ldg(fb + b100 + q);
            ax = fmaf(v.x, w100, ax); ay = fmaf(v.y, w100, ay);
            az = fmaf(v.z, w100, az); aw = fmaf(v.w, w100, aw);
            v = __ldg(fb + b101 + q);
            ax = fmaf(v.x, w101, ax); ay = fmaf(v.y, w101, ay);
            az = fmaf(v.z, w101, az); aw = fmaf(v.w, w101, aw);
            v = __ldg(fb + b110 + q);
            ax = fmaf(v.x, w110, ax); ay = fmaf(v.y, w110, ay);
            az = fmaf(v.z, w110, az); aw = fmaf(v.w, w110, aw);
            v = __ldg(fb + b111 + q);
            ax = fmaf(v.x, w111, ax); ay = fmaf(v.y, w111, ay);
            az = fmaf(v.z, w111, az); aw = fmaf(v.w, w111, aw);
            x[4*q+0] = ax; x[4*q+1] = ay; x[4*q+2] = az; x[4*q+3] = aw;
        }
    }
}

// ---------------- main fused kernel: 1 block = 1 ray, 128 threads, 4 blocks/SM ----
#define XP 20   // u32 pitch of X rows (conflict-free fragment loads)

__global__ __launch_bounds__(128, 4)
void nerf_mma4(const float* __restrict__ rays_o,
               const float* __restrict__ rays_d,
               const float* __restrict__ G1,
               float* __restrict__ outp)
{
    __shared__ u32   Xs[128*XP];     // X features, row = sample
    __shared__ float shE[16];        // SH encoding (per-ray uniform)
    __shared__ float sigs[128];      // raw sigma per sample
    __shared__ float rgbs[128][4];   // sigmoid(col) per sample

    const int ray = blockIdx.x;
    const int tid = threadIdx.x;

    const float ox = __ldg(rays_o + ray*3+0), oy = __ldg(rays_o + ray*3+1),
                oz = __ldg(rays_o + ray*3+2);
    float dx = __ldg(rays_d + ray*3+0), dy = __ldg(rays_d + ray*3+1),
          dz = __ldg(rays_d + ray*3+2);
    const float dn = sqrtf(dx*dx + dy*dy + dz*dz);
    dx /= dn; dy /= dn; dz /= dn;

    const float b  = ox*dx + oy*dy + oz*dz;
    const float cc = ox*ox + oy*oy + oz*oz - RADIUS_F*RADIUS_F;
    const float disc = b*b - cc;
    const bool hit = disc > 0.0f;
    const float sq = sqrtf(hit ? disc : 1.0f);
    const float tmin = hit ? fmaxf(-b - sq, 0.0f) : 0.0f;
    const float tmax = hit ? (-b + sq) : 0.0f;

    // ---- SH encoding to shared (thread 0)
    if (tid == 0) {
        const float x = dx, y = dy, z = dz;
        const float xx = x*x, yy = y*y, zz = z*z;
        const float xy = x*y, yz = y*z, xz = x*z;
        shE[0]  = 0.28209479177387814f;
        shE[1]  = -0.48860251190291987f*y;
        shE[2]  =  0.48860251190291987f*z;
        shE[3]  = -0.48860251190291987f*x;
        shE[4]  =  1.0925484305920792f*xy;
        shE[5]  = -1.0925484305920792f*yz;
        shE[6]  =  0.94617469575756f*zz - 0.31539156525252f;
        shE[7]  = -1.0925484305920792f*xz;
        shE[8]  =  0.5462742152960396f*(xx - yy);
        shE[9]  =  0.5900435899266435f*y*(-3.0f*xx + yy);
        shE[10] =  2.890611442640554f*xy*z;
        shE[11] =  0.4570457994644657f*y*(1.0f - 5.0f*zz);
        shE[12] =  0.3731763325901154f*z*(5.0f*zz - 3.0f);
        shE[13] =  0.4570457994644657f*x*(1.0f - 5.0f*zz);
        shE[14] =  1.445305721320277f*z*(xx - yy);
        shE[15] =  0.5900435899266435f*x*(-xx + 3.0f*yy);
    }

    // ---- sampling phase: 128 threads, one sample each
    {
        const int s = tid;
        const float tmid = tmin + ((float)s + 0.5f) * STEPSZ;
        const bool m = hit && (tmid <= tmax);
        u32* xrow = Xs + s*XP;
        if (m) {
            float xf[32];
            sample_feats(G1, (ox + dx*tmid)/RADIUS_F, (oy + dy*tmid)/RADIUS_F,
                         (oz + dz*tmid)/RADIUS_F, xf);
            #pragma unroll
            for (int i = 0; i < 16; i++) xrow[i] = packbf(xf[2*i], xf[2*i+1]);
        } else {
            // clean state for (possibly skipped) masked samples
            #pragma unroll
            for (int i = 0; i < 16; i++) xrow[i] = 0u;
            sigs[s] = 0.0f;
            rgbs[s][0] = 0.0f; rgbs[s][1] = 0.0f; rgbs[s][2] = 0.0f;
        }
    }
    __syncthreads();

    // ---- MLP phase: 8 tiles of 16 samples; warp w does tiles w and w+4.
    // mask is a prefix -> tile active iff its first sample is inside.
    {
        const int wid = tid >> 5, lane = tid & 31;
        const int r = lane >> 2, c = lane & 3;

        #pragma unroll
        for (int ti = 0; ti < 2; ti++) {
            const int t = wid + ti*4;          // tile 0..7
            const bool active = hit &&
                (tmin + ((float)(t*16) + 0.5f)*STEPSZ <= tmax);
            if (!active) continue;

            const int s0 = t*16 + r, s1 = s0 + 8;
            u32 bfr[2];

            // A fragments of X (K=32 -> 2 k-tiles)
            u32 aX[2][4];
            #pragma unroll
            for (int kt = 0; kt < 2; kt++) {
                aX[kt][0] = Xs[s0*XP + kt*8 + c];
                aX[kt][1] = Xs[s1*XP + kt*8 + c];
                aX[kt][2] = Xs[s0*XP + kt*8 + c + 4];
                aX[kt][3] = Xs[s1*XP + kt*8 + c + 4];
            }

            // ---- L0: X(16x32) @ W0 -> 16x128
            float acc[16][4];
            #pragma unroll
            for (int nt = 0; nt < 16; nt++) {
                acc[nt][0] = acc[nt][1] = acc[nt][2] = acc[nt][3] = 0.0f;
                #pragma unroll
                for (int kt = 0; kt < 2; kt++) {
                    ldb(bfr, PB_L0, nt, kt, 2, lane);
                    mma_bf16(acc[nt], aX[kt], bfr);
                }
            }
            u32 ah[8][4];
            #pragma unroll
            for (int kt = 0; kt < 8; kt++) {
                ah[kt][0] = packbf_relu(acc[2*kt][0],   acc[2*kt][1]);
                ah[kt][1] = packbf_relu(acc[2*kt][2],   acc[2*kt][3]);
                ah[kt][2] = packbf_relu(acc[2*kt+1][0], acc[2*kt+1][1]);
                ah[kt][3] = packbf_relu(acc[2*kt+1][2], acc[2*kt+1][3]);
            }

            // ---- L1: H1 @ W1 -> 16x128
            #pragma unroll
            for (int nt = 0; nt < 16; nt++) {
                acc[nt][0] = acc[nt][1] = acc[nt][2] = acc[nt][3] = 0.0f;
                #pragma unroll
                for (int kt = 0; kt < 8; kt++) {
                    ldb(bfr, PB_L1, nt, kt, 8, lane);
                    mma_bf16(acc[nt], ah[kt], bfr);
                }
            }
            #pragma unroll
            for (int kt = 0; kt < 8; kt++) {
                ah[kt][0] = packbf_relu(acc[2*kt][0],   acc[2*kt][1]);
                ah[kt][1] = packbf_relu(acc[2*kt][2],   acc[2*kt][3]);
                ah[kt][2] = packbf_relu(acc[2*kt+1][0], acc[2*kt+1][1]);
                ah[kt][3] = packbf_relu(acc[2*kt+1][2], acc[2*kt+1][3]);
            }

            // ---- L2: H2 @ W2' -> 16x16  (cols rotated; col15 = sigma)
            float dsig[2][4];
            #pragma unroll
            for (int nt = 0; nt < 2; nt++) {
                dsig[nt][0] = dsig[nt][1] = dsig[nt][2] = dsig[nt][3] = 0.0f;
                #pragma unroll
                for (int kt = 0; kt < 8; kt++) {
                    ldb(bfr, PB_L2, nt, kt, 8, lane);
                    mma_bf16(dsig[nt], ah[kt], bfr);
                }
            }
            if (c == 3) {
                sigs[s0] = dsig[1][1];
                sigs[s1] = dsig[1][3];
            }

            // ---- color input fragments: k-tile0 = enc (uniform rows), k-tile1 = dsig raw
            u32 ae0[4], ae1[4];
            {
                u32 lo = packbf(shE[2*c],     shE[2*c+1]);
                u32 hi = packbf(shE[8 + 2*c], shE[9 + 2*c]);
                ae0[0] = lo; ae0[1] = lo; ae0[2] = hi; ae0[3] = hi;
            }
            ae1[0] = packbf(dsig[0][0], dsig[0][1]);
            ae1[1] = packbf(dsig[0][2], dsig[0][3]);
            ae1[2] = packbf(dsig[1][0], dsig[1][1]);
            ae1[3] = packbf(dsig[1][2], dsig[1][3]);

            // ---- C0: Cin(16x32) @ Wc0 -> 16x64
            float dc[8][4];
            #pragma unroll
            for (int nt = 0; nt < 8; nt++) {
                dc[nt][0] = dc[nt][1] = dc[nt][2] = dc[nt][3] = 0.0f;
                ldb(bfr, PB_C0, nt, 0, 2, lane); mma_bf16(dc[nt], ae0, bfr);
                ldb(bfr, PB_C0, nt, 1, 2, lane); mma_bf16(dc[nt], ae1, bfr);
            }
            u32 ag[4][4];
            #pragma unroll
            for (int kt = 0; kt < 4; kt++) {
                ag[kt][0] = packbf_relu(dc[2*kt][0],   dc[2*kt][1]);
                ag[kt][1] = packbf_relu(dc[2*kt][2],   dc[2*kt][3]);
                ag[kt][2] = packbf_relu(dc[2*kt+1][0], dc[2*kt+1][1]);
                ag[kt][3] = packbf_relu(dc[2*kt+1][2], dc[2*kt+1][3]);
            }

            // ---- C1: G1h @ Wc1 -> 16x64
            #pragma unroll
            for (int nt = 0; nt < 8; nt++) {
                dc[nt][0] = dc[nt][1] = dc[nt][2] = dc[nt][3] = 0.0f;
                #pragma unroll
                for (int kt = 0; kt < 4; kt++) {
                    ldb(bfr, PB_C1, nt, kt, 4, lane);
                    mma_bf16(dc[nt], ag[kt], bfr);
                }
            }
            #pragma unroll
            for (int kt = 0; kt < 4; kt++) {
                ag[kt][0] = packbf_relu(dc[2*kt][0],   dc[2*kt][1]);
                ag[kt][1] = packbf_relu(dc[2*kt][2],   dc[2*kt][3]);
                ag[kt][2] = packbf_relu(dc[2*kt+1][0], dc[2*kt+1][1]);
                ag[kt][3] = packbf_relu(dc[2*kt+1][2], dc[2*kt+1][3]);
            }

            // ---- C2: G2h @ Wc2 -> 16x8 (cols 0,1,2 = r,g,b)
            float drgb[4] = {0.0f, 0.0f, 0.0f, 0.0f};
            #pragma unroll
            for (int kt = 0; kt < 4; kt++) {
                ldb(bfr, PB_C2, 0, kt, 4, lane);
                mma_bf16(drgb, ag[kt], bfr);
            }
            if (c == 0) {   // cols 0,1 -> R,G
                rgbs[s0][0] = sigm(drgb[0]); rgbs[s0][1] = sigm(drgb[1]);
                rgbs[s1][0] = sigm(drgb[2]); rgbs[s1][1] = sigm(drgb[3]);
            }
            if (c == 1) {   // col 2 -> B
                rgbs[s0][2] = sigm(drgb[0]);
                rgbs[s1][2] = sigm(drgb[2]);
            }
        }
    }
    __syncthreads();

    // ---- compositing: warp 0 parallel scan (4 samples per lane, in order)
    if (tid < 32) {
        const int lane = tid;
        float Tl = 1.0f;
        float rr = 0.0f, gg = 0.0f, bb = 0.0f, ws = 0.0f;
        #pragma unroll
        for (int j = 0; j < 4; j++) {
            const int i = lane*4 + j;
            const float sg = fmaxf(sigs[i], 0.0f);
            const float a  = 1.0f - __expf(-sg * STEPSZ);
            const float w  = a * Tl;
            rr += w * rgbs[i][0];
            gg += w * rgbs[i][1];
            bb += w * rgbs[i][2];
            ws += w;
            Tl *= (1.0f - a + 1e-10f);
        }
        float inc = Tl;
        #pragma unroll
        for (int off = 1; off < 32; off <<= 1) {
            float v = __shfl_up_sync(0xFFFFFFFFu, inc, off);
            if (lane >= off) inc *= v;
        }
        float exc = __shfl_up_sync(0xFFFFFFFFu, inc, 1);
        if (lane == 0) exc = 1.0f;
        rr *= exc; gg *= exc; bb *= exc; ws *= exc;
        #pragma unroll
        for (int off = 16; off > 0; off >>= 1) {
            rr += __shfl_down_sync(0xFFFFFFFFu, rr, off);
            gg += __shfl_down_sync(0xFFFFFFFFu, gg, off);
            bb += __shfl_down_sync(0xFFFFFFFFu, bb, off);
            ws += __shfl_down_sync(0xFFFFFFFFu, ws, off);
        }
        if (lane == 0) {
            const float bg = 1.0f - ws;
            outp[ray*3+0] = rr + bg;
            outp[ray*3+1] = gg + bg;
            outp[ray*3+2] = bb + bg;
        }
    }
}

// ---------------- launch ----------------
extern "C" void kernel_launch(void* const* d_in, const int* in_sizes, int n_in,
                              void* d_out, int out_size)
{
    const float* rays_o = (const float*)d_in[0];
    const float* rays_d = (const float*)d_in[1];
    const float* G1     = (const float*)d_in[2];
    const float* F      = (const float*)d_in[3];
    const float* W0     = (const float*)d_in[4];
    const float* W1     = (const float*)d_in[5];
    const float* W2     = (const float*)d_in[6];
    const float* Wc0    = (const float*)d_in[7];
    const float* Wc1    = (const float*)d_in[8];
    const float* Wc2    = (const float*)d_in[9];
    float* outp = (float*)d_out;

    const int B = in_sizes[0] / 3;

    prep_kernel<<<(131072 + 14592 + 255)/256, 256>>>(F, W0, W1, W2, Wc0, Wc1, Wc2);

    nerf_mma4<<<B, 128>>>(rays_o, rays_d, G1, outp);
}

// round 15
// speedup vs baseline: 1.1316x; 1.0290x over previous
#include <cuda_runtime.h>
#include <cuda_bf16.h>
#include <math.h>

typedef unsigned int u32;

#define RADIUS_F 1.3f
#define STEPSZ   0.02f

// ---------------- global scratch (no allocs allowed) ----------------
__device__ float g_Ft[131072];      // F transposed (idx, 32ch)
__device__ u32   g_pack[14592];     // all weights in bf16 B-fragment order

// pack-buffer bases (u32 units)
#define PB_L0 0        // W0  K=32  N=128  KT=2 NT=16 -> 2048
#define PB_L1 2048     // W1  K=128 N=128  KT=8 NT=16 -> 8192
#define PB_L2 10240    // W2  K=128 N=16   KT=8 NT=2  -> 1024 (cols rotated; col15 = sigma)
#define PB_C0 11264    // Wc0 K=32(31+pad) N=64 KT=2 NT=8 -> 1024
#define PB_C1 12288    // Wc1 K=64  N=64   KT=4 NT=8 -> 2048
#define PB_C2 14336    // Wc2 K=64  N=8(3+pad) KT=4 NT=1 -> 256

// ---------------- single merged prep kernel ----------------
__device__ __forceinline__ void pack_one(const float* __restrict__ W, int base, int j,
                                         int KT, int Korig, int Norig, int rowstride,
                                         int sig_reorder)
{
    int r    = j & 1;
    int lane = (j >> 1) & 31;
    int t    = j >> 6;           // = nt*KT + kt
    int kt   = t % KT;
    int nt   = t / KT;
    int k = kt*16 + (lane & 3)*2 + r*8;
    int n = nt*8 + (lane >> 2);
    int nc = sig_reorder ? ((n == 15) ? 0 : n + 1) : n;
    float w0 = (k     < Korig && nc < Norig) ? W[k*rowstride + nc]     : 0.0f;
    float w1 = (k + 1 < Korig && nc < Norig) ? W[(k+1)*rowstride + nc] : 0.0f;
    __nv_bfloat162 p = __floats2bfloat162_rn(w0, w1);
    g_pack[base + j] = *(u32*)&p;
}

__global__ void prep_kernel(const float* __restrict__ F,
                            const float* __restrict__ W0,
                            const float* __restrict__ W1,
                            const float* __restrict__ W2,
                            const float* __restrict__ Wc0,
                            const float* __restrict__ Wc1,
                            const float* __restrict__ Wc2)
{
    int idx = blockIdx.x * blockDim.x + threadIdx.x;
    if (idx < 131072) {
        int ch  = idx >> 12;
        int e   = idx & 4095;
        g_Ft[e * 32 + ch] = F[idx];
        return;
    }
    int j = idx - 131072;
    if (j < 2048)       pack_one(W0,  PB_L0, j,         2, 32,  128, 128, 0);
    else if (j < 10240) pack_one(W1,  PB_L1, j - 2048,  8, 128, 128, 128, 0);
    else if (j < 11264) pack_one(W2,  PB_L2, j - 10240, 8, 128, 16,  16,  1);
    else if (j < 12288) pack_one(Wc0, PB_C0, j - 11264, 2, 31,  64,  64,  0);
    else if (j < 14336) pack_one(Wc1, PB_C1, j - 12288, 4, 64,  64,  64,  0);
    else if (j < 14592) pack_one(Wc2, PB_C2, j - 14336, 4, 64,  3,   3,   0);
}

// ---------------- device helpers ----------------
__device__ __forceinline__ u32 packbf(float lo, float hi) {
    __nv_bfloat162 p = __floats2bfloat162_rn(lo, hi);
    return *(u32*)&p;
}
__device__ __forceinline__ u32 packbf_relu(float lo, float hi) {
    return packbf(fmaxf(lo, 0.0f), fmaxf(hi, 0.0f));
}
__device__ __forceinline__ void mma_bf16(float* d, const u32* a, const u32* b) {
    asm volatile(
        "mma.sync.aligned.m16n8k16.row.col.f32.bf16.bf16.f32 "
        "{%0,%1,%2,%3},{%4,%5,%6,%7},{%8,%9},{%0,%1,%2,%3};"
        : "+f"(d[0]), "+f"(d[1]), "+f"(d[2]), "+f"(d[3])
        : "r"(a[0]), "r"(a[1]), "r"(a[2]), "r"(a[3]), "r"(b[0]), "r"(b[1]));
}
__device__ __forceinline__ void ldb(u32* b, int base, int nt, int kt, int KT, int lane) {
    const uint2* p = (const uint2*)(g_pack + base + (((nt*KT + kt) << 5) + lane)*2);
    uint2 v = __ldg(p);
    b[0] = v.x; b[1] = v.y;
}
__device__ __forceinline__ float sigm(float v) {
    return __fdividef(1.0f, 1.0f + __expf(-v));
}

// G1 trilinear (3ch, 256^3) then F trilinear (32ch via g_Ft) -> x[32]
__device__ __forceinline__ void sample_feats(const float* __restrict__ G1,
                                             float px, float py, float pz,
                                             float* __restrict__ x)
{
    float gi[3];
    {
        float fx = fminf(fmaxf((px + 1.0f)*0.5f*255.0f, 0.0f), 255.0f);
        float fy = fminf(fmaxf((py + 1.0f)*0.5f*255.0f, 0.0f), 255.0f);
        float fz = fminf(fmaxf((pz + 1.0f)*0.5f*255.0f, 0.0f), 255.0f);
        int x0 = (int)floorf(fx), y0 = (int)floorf(fy), z0 = (int)floorf(fz);
        int x1 = min(x0+1, 255), y1 = min(y0+1, 255), z1 = min(z0+1, 255);
        float wx = fx - (float)x0, wy = fy - (float)y0, wz = fz - (float)z0;
        int o00 = z0*65536 + y0*256;
        int o01 = z0*65536 + y1*256;
        int o10 = z1*65536 + y0*256;
        int o11 = z1*65536 + y1*256;
        #pragma unroll
        for (int ch = 0; ch < 3; ch++) {
            const float* g = G1 + ch*16777216;
            float v000 = __ldg(g + o00 + x0), v001 = __ldg(g + o00 + x1);
            float v010 = __ldg(g + o01 + x0), v011 = __ldg(g + o01 + x1);
            float v100 = __ldg(g + o10 + x0), v101 = __ldg(g + o10 + x1);
            float v110 = __ldg(g + o11 + x0), v111 = __ldg(g + o11 + x1);
            float c00 = v000*(1.0f-wx) + v001*wx;
            float c01 = v010*(1.0f-wx) + v011*wx;
            float c10 = v100*(1.0f-wx) + v101*wx;
            float c11 = v110*(1.0f-wx) + v111*wx;
            float c0  = c00*(1.0f-wy) + c01*wy;
            float c1  = c10*(1.0f-wy) + c11*wy;
            gi[ch] = c0*(1.0f-wz) + c1*wz;
        }
    }
    {
        float fx = fminf(fmaxf((gi[0] + 1.0f)*7.5f, 0.0f), 15.0f);
        float fy = fminf(fmaxf((gi[1] + 1.0f)*7.5f, 0.0f), 15.0f);
        float fz = fminf(fmaxf((gi[2] + 1.0f)*7.5f, 0.0f), 15.0f);
        int x0 = (int)floorf(fx), y0 = (int)floorf(fy), z0 = (int)floorf(fz);
        int x1 = min(x0+1, 15), y1 = min(y0+1, 15), z1 = min(z0+1, 15);
        float wx = fx - (float)x0, wy = fy - (float)y0, wz = fz - (float)z0;
        float mx = 1.0f - wx, my = 1.0f - wy, mz = 1.0f - wz;
        float w000 = mx*my*mz, w001 = wx*my*mz;
        float w010 = mx*wy*mz, w011 = wx*wy*mz;
        float w100 = mx*my*wz, w101 = wx*my*wz;
        float w110 = mx*wy*wz, w111 = wx*wy*wz;
        const float4* fb = (const float4*)g_Ft;
        int b000 = (z0*256 + y0*16 + x0)*8;
        int b001 = (z0*256 + y0*16 + x1)*8;
        int b010 = (z0*256 + y1*16 + x0)*8;
        int b011 = (z0*256 + y1*16 + x1)*8;
        int b100 = (z1*256 + y0*16 + x0)*8;
        int b101 = (z1*256 + y0*16 + x1)*8;
        int b110 = (z1*256 + y1*16 + x0)*8;
        int b111 = (z1*256 + y1*16 + x1)*8;
        #pragma unroll
        for (int q = 0; q < 8; q++) {
            float4 v = __ldg(fb + b000 + q);
            float ax = v.x*w000, ay = v.y*w000, az = v.z*w000, aw = v.w*w000;
            v = __ldg(fb + b001 + q);
            ax = fmaf(v.x, w001, ax); ay = fmaf(v.y, w001, ay);
            az = fmaf(v.z, w001, az); aw = fmaf(v.w, w001, aw);
            v = __ldg(fb + b010 + q);
            ax = fmaf(v.x, w010, ax); ay = fmaf(v.y, w010, ay);
            az = fmaf(v.z, w010, az); aw = fmaf(v.w, w010, aw);
            v = __ldg(fb + b011 + q);
            ax = fmaf(v.x, w011, ax); ay = fmaf(v.y, w011, ay);
            az = fmaf(v.z, w011, az); aw = fmaf(v.w, w011, aw);
            v = __ldg(fb + b100 + q);
            ax = fmaf(v.x, w100, ax); ay = fmaf(v.y, w100, ay);
            az = fmaf(v.z, w100, az); aw = fmaf(v.w, w100, aw);
            v = __ldg(fb + b101 + q);
            ax = fmaf(v.x, w101, ax); ay = fmaf(v.y, w101, ay);
            az = fmaf(v.z, w101, az); aw = fmaf(v.w, w101, aw);
            v = __ldg(fb + b110 + q);
            ax = fmaf(v.x, w110, ax); ay = fmaf(v.y, w110, ay);
            az = fmaf(v.z, w110, az); aw = fmaf(v.w, w110, aw);
            v = __ldg(fb + b111 + q);
            ax = fmaf(v.x, w111, ax); ay = fmaf(v.y, w111, ay);
            az = fmaf(v.z, w111, az); aw = fmaf(v.w, w111, aw);
            x[4*q+0] = ax; x[4*q+1] = ay; x[4*q+2] = az; x[4*q+3] = aw;
        }
    }
}

// ---------------- main fused kernel: 1 block = 1 ray, 128 threads, 4 blocks/SM ----
// Warp-autonomous: warp w samples EXACTLY the 32 rows its two tiles (w, w+4)
// consume, so sampling -> MLP needs only __syncwarp(), no block barrier.
#define XP 20   // u32 pitch of X rows (conflict-free fragment loads)

__global__ __launch_bounds__(128, 4)
void nerf_mma5(const float* __restrict__ rays_o,
               const float* __restrict__ rays_d,
               const float* __restrict__ G1,
               float* __restrict__ outp)
{
    __shared__ u32   Xs[128*XP];     // X features, row = sample
    __shared__ float sigs[128];      // raw sigma per sample
    __shared__ float rgbs[128][4];   // sigmoid(col) per sample

    const int ray = blockIdx.x;
    const int tid = threadIdx.x;
    const int wid = tid >> 5, lane = tid & 31;

    const float ox = __ldg(rays_o + ray*3+0), oy = __ldg(rays_o + ray*3+1),
                oz = __ldg(rays_o + ray*3+2);
    float dx = __ldg(rays_d + ray*3+0), dy = __ldg(rays_d + ray*3+1),
          dz = __ldg(rays_d + ray*3+2);
    const float dn = sqrtf(dx*dx + dy*dy + dz*dz);
    dx /= dn; dy /= dn; dz /= dn;

    const float b  = ox*dx + oy*dy + oz*dz;
    const float cc = ox*ox + oy*oy + oz*oz - RADIUS_F*RADIUS_F;
    const float disc = b*b - cc;
    const bool hit = disc > 0.0f;
    const float sq = sqrtf(hit ? disc : 1.0f);
    const float tmin = hit ? fmaxf(-b - sq, 0.0f) : 0.0f;
    const float tmax = hit ? (-b + sq) : 0.0f;

    // ---- sampling: lane l of warp w owns row 16w + (l&15) + (l>=16 ? 64 : 0)
    // (i.e. the rows of tiles w and w+4 -- exactly what this warp's MLP reads)
    {
        const int srow = wid*16 + (lane & 15) + ((lane >> 4) << 6);
        const float tmid = tmin + ((float)srow + 0.5f) * STEPSZ;
        const bool m = hit && (tmid <= tmax);
        u32* xrow = Xs + srow*XP;
        if (m) {
            float xf[32];
            sample_feats(G1, (ox + dx*tmid)/RADIUS_F, (oy + dy*tmid)/RADIUS_F,
                         (oz + dz*tmid)/RADIUS_F, xf);
            #pragma unroll
            for (int i = 0; i < 16; i++) xrow[i] = packbf(xf[2*i], xf[2*i+1]);
        } else {
            #pragma unroll
            for (int i = 0; i < 16; i++) xrow[i] = 0u;
            sigs[srow] = 0.0f;
            rgbs[srow][0] = 0.0f; rgbs[srow][1] = 0.0f; rgbs[srow][2] = 0.0f;
        }
    }
    __syncwarp();

    // ---- MLP phase: warp w does tiles w and w+4 (prefix mask -> tile active
    // iff its first sample is inside). No cross-warp dependency.
    {
        const int r = lane >> 2, c = lane & 3;

        // per-lane SH fragment values (uniform inputs; each lane needs only
        // columns 2c,2c+1 (lo) and 8+2c,9+2c (hi) of the encoding row)
        u32 ae_lo, ae_hi;
        {
            const float x = dx, y = dy, z = dz;
            const float xx = x*x, yy = y*y, zz = z*z;
            const float xy = x*y, yz = y*z, xz = x*z;
            switch (c) {
            case 0:
                ae_lo = packbf(0.28209479177387814f, -0.48860251190291987f*y);
                ae_hi = packbf(0.5462742152960396f*(xx - yy),
                               0.5900435899266435f*y*(-3.0f*xx + yy));
                break;
            case 1:
                ae_lo = packbf(0.48860251190291987f*z, -0.48860251190291987f*x);
                ae_hi = packbf(2.890611442640554f*xy*z,
                               0.4570457994644657f*y*(1.0f - 5.0f*zz));
                break;
            case 2:
                ae_lo = packbf(1.0925484305920792f*xy, -1.0925484305920792f*yz);
                ae_hi = packbf(0.3731763325901154f*z*(5.0f*zz - 3.0f),
                               0.4570457994644657f*x*(1.0f - 5.0f*zz));
                break;
            default:
                ae_lo = packbf(0.94617469575756f*zz - 0.31539156525252f,
                               -1.0925484305920792f*xz);
                ae_hi = packbf(1.445305721320277f*z*(xx - yy),
                               0.5900435899266435f*x*(-xx + 3.0f*yy));
                break;
            }
        }

        #pragma unroll
        for (int ti = 0; ti < 2; ti++) {
            const int t = wid + ti*4;          // tile 0..7
            const bool active = hit &&
                (tmin + ((float)(t*16) + 0.5f)*STEPSZ <= tmax);
            if (!active) continue;

            const int s0 = t*16 + r, s1 = s0 + 8;
            u32 bfr[2];

            // A fragments of X (K=32 -> 2 k-tiles)
            u32 aX[2][4];
            #pragma unroll
            for (int kt = 0; kt < 2; kt++) {
                aX[kt][0] = Xs[s0*XP + kt*8 + c];
                aX[kt][1] = Xs[s1*XP + kt*8 + c];
                aX[kt][2] = Xs[s0*XP + kt*8 + c + 4];
                aX[kt][3] = Xs[s1*XP + kt*8 + c + 4];
            }

            // ---- L0: X(16x32) @ W0 -> 16x128
            float acc[16][4];
            #pragma unroll
            for (int nt = 0; nt < 16; nt++) {
                acc[nt][0] = acc[nt][1] = acc[nt][2] = acc[nt][3] = 0.0f;
                #pragma unroll
                for (int kt = 0; kt < 2; kt++) {
                    ldb(bfr, PB_L0, nt, kt, 2, lane);
                    mma_bf16(acc[nt], aX[kt], bfr);
                }
            }
            u32 ah[8][4];
            #pragma unroll
            for (int kt = 0; kt < 8; kt++) {
                ah[kt][0] = packbf_relu(acc[2*kt][0],   acc[2*kt][1]);
                ah[kt][1] = packbf_relu(acc[2*kt][2],   acc[2*kt][3]);
                ah[kt][2] = packbf_relu(acc[2*kt+1][0], acc[2*kt+1][1]);
                ah[kt][3] = packbf_relu(acc[2*kt+1][2], acc[2*kt+1][3]);
            }

            // ---- L1: H1 @ W1 -> 16x128
            #pragma unroll
            for (int nt = 0; nt < 16; nt++) {
                acc[nt][0] = acc[nt][1] = acc[nt][2] = acc[nt][3] = 0.0f;
                #pragma unroll
                for (int kt = 0; kt < 8; kt++) {
                    ldb(bfr, PB_L1, nt, kt, 8, lane);
                    mma_bf16(acc[nt], ah[kt], bfr);
                }
            }
            #pragma unroll
            for (int kt = 0; kt < 8; kt++) {
                ah[kt][0] = packbf_relu(acc[2*kt][0],   acc[2*kt][1]);
                ah[kt][1] = packbf_relu(acc[2*kt][2],   acc[2*kt][3]);
                ah[kt][2] = packbf_relu(acc[2*kt+1][0], acc[2*kt+1][1]);
                ah[kt][3] = packbf_relu(acc[2*kt+1][2], acc[2*kt+1][3]);
            }

            // ---- L2: H2 @ W2' -> 16x16  (cols rotated; col15 = sigma)
            float dsig[2][4];
            #pragma unroll
            for (int nt = 0; nt < 2; nt++) {
                dsig[nt][0] = dsig[nt][1] = dsig[nt][2] = dsig[nt][3] = 0.0f;
                #pragma unroll
                for (int kt = 0; kt < 8; kt++) {
                    ldb(bfr, PB_L2, nt, kt, 8, lane);
                    mma_bf16(dsig[nt], ah[kt], bfr);
                }
            }
            if (c == 3) {
                sigs[s0] = dsig[1][1];
                sigs[s1] = dsig[1][3];
            }

            // ---- color input fragments: k-tile0 = enc (uniform rows), k-tile1 = dsig raw
            u32 ae0[4], ae1[4];
            ae0[0] = ae_lo; ae0[1] = ae_lo; ae0[2] = ae_hi; ae0[3] = ae_hi;
            ae1[0] = packbf(dsig[0][0], dsig[0][1]);
            ae1[1] = packbf(dsig[0][2], dsig[0][3]);
            ae1[2] = packbf(dsig[1][0], dsig[1][1]);
            ae1[3] = packbf(dsig[1][2], dsig[1][3]);

            // ---- C0: Cin(16x32) @ Wc0 -> 16x64
            float dc[8][4];
            #pragma unroll
            for (int nt = 0; nt < 8; nt++) {
                dc[nt][0] = dc[nt][1] = dc[nt][2] = dc[nt][3] = 0.0f;
                ldb(bfr, PB_C0, nt, 0, 2, lane); mma_bf16(dc[nt], ae0, bfr);
                ldb(bfr, PB_C0, nt, 1, 2, lane); mma_bf16(dc[nt], ae1, bfr);
            }
            u32 ag[4][4];
            #pragma unroll
            for (int kt = 0; kt < 4; kt++) {
                ag[kt][0] = packbf_relu(dc[2*kt][0],   dc[2*kt][1]);
                ag[kt][1] = packbf_relu(dc[2*kt][2],   dc[2*kt][3]);
                ag[kt][2] = packbf_relu(dc[2*kt+1][0], dc[2*kt+1][1]);
                ag[kt][3] = packbf_relu(dc[2*kt+1][2], dc[2*kt+1][3]);
            }

            // ---- C1: G1h @ Wc1 -> 16x64
            #pragma unroll
            for (int nt = 0; nt < 8; nt++) {
                dc[nt][0] = dc[nt][1] = dc[nt][2] = dc[nt][3] = 0.0f;
                #pragma unroll
                for (int kt = 0; kt < 4; kt++) {
                    ldb(bfr, PB_C1, nt, kt, 4, lane);
                    mma_bf16(dc[nt], ag[kt], bfr);
                }
            }
            #pragma unroll
            for (int kt = 0; kt < 4; kt++) {
                ag[kt][0] = packbf_relu(dc[2*kt][0],   dc[2*kt][1]);
                ag[kt][1] = packbf_relu(dc[2*kt][2],   dc[2*kt][3]);
                ag[kt][2] = packbf_relu(dc[2*kt+1][0], dc[2*kt+1][1]);
                ag[kt][3] = packbf_relu(dc[2*kt+1][2], dc[2*kt+1][3]);
            }

            // ---- C2: G2h @ Wc2 -> 16x8 (cols 0,1,2 = r,g,b)
            float drgb[4] = {0.0f, 0.0f, 0.0f, 0.0f};
            #pragma unroll
            for (int kt = 0; kt < 4; kt++) {
                ldb(bfr, PB_C2, 0, kt, 4, lane);
                mma_bf16(drgb, ag[kt], bfr);
            }
            if (c == 0) {   // cols 0,1 -> R,G
                rgbs[s0][0] = sigm(drgb[0]); rgbs[s0][1] = sigm(drgb[1]);
                rgbs[s1][0] = sigm(drgb[2]); rgbs[s1][1] = sigm(drgb[3]);
            }
            if (c == 1) {   // col 2 -> B
                rgbs[s0][2] = sigm(drgb[0]);
                rgbs[s1][2] = sigm(drgb[2]);
            }
        }
    }
    __syncthreads();

    // ---- compositing: warp 0 parallel scan (4 samples per lane, in order)
    if (tid < 32) {
        const int l = tid;
        float Tl = 1.0f;
        float rr = 0.0f, gg = 0.0f, bb = 0.0f, ws = 0.0f;
        #pragma unroll
        for (int j = 0; j < 4; j++) {
            const int i = l*4 + j;
            const float sg = fmaxf(sigs[i], 0.0f);
            const float a  = 1.0f - __expf(-sg * STEPSZ);
            const float w  = a * Tl;
            rr += w * rgbs[i][0];
            gg += w * rgbs[i][1];
            bb += w * rgbs[i][2];
            ws += w;
            Tl *= (1.0f - a + 1e-10f);
        }
        float inc = Tl;
        #pragma unroll
        for (int off = 1; off < 32; off <<= 1) {
            float v = __shfl_up_sync(0xFFFFFFFFu, inc, off);
            if (l >= off) inc *= v;
        }
        float exc = __shfl_up_sync(0xFFFFFFFFu, inc, 1);
        if (l == 0) exc = 1.0f;
        rr *= exc; gg *= exc; bb *= exc; ws *= exc;
        #pragma unroll
        for (int off = 16; off > 0; off >>= 1) {
            rr += __shfl_down_sync(0xFFFFFFFFu, rr, off);
            gg += __shfl_down_sync(0xFFFFFFFFu, gg, off);
            bb += __shfl_down_sync(0xFFFFFFFFu, bb, off);
            ws += __shfl_down_sync(0xFFFFFFFFu, ws, off);
        }
        if (l == 0) {
            const float bg = 1.0f - ws;
            outp[ray*3+0] = rr + bg;
            outp[ray*3+1] = gg + bg;
            outp[ray*3+2] = bb + bg;
        }
    }
}

// ---------------- launch ----------------
extern "C" void kernel_launch(void* const* d_in, const int* in_sizes, int n_in,
                              void* d_out, int out_size)
{
    const float* rays_o = (const float*)d_in[0];
    const float* rays_d = (const float*)d_in[1];
    const float* G1     = (const float*)d_in[2];
    const float* F      = (const float*)d_in[3];
    const float* W0     = (const float*)d_in[4];
    const float* W1     = (const float*)d_in[5];
    const float* W2     = (const float*)d_in[6];
    const float* Wc0    = (const float*)d_in[7];
    const float* Wc1    = (const float*)d_in[8];
    const float* Wc2    = (const float*)d_in[9];
    float* outp = (float*)d_out;

    const int B = in_sizes[0] / 3;

    prep_kernel<<<(131072 + 14592 + 255)/256, 256>>>(F, W0, W1, W2, Wc0, Wc1, Wc2);

    nerf_mma5<<<B, 128>>>(rays_o, rays_d, G1, outp);
}